// round 7
// baseline (speedup 1.0000x reference)
#include <cuda_runtime.h>
#include <cuda_bf16.h>
#include <math.h>
#include <float.h>
#include <stdint.h>

// Shapes (fixed): z_e [32,64,64,64] f32, emb [512,64] f32.
#define N_TOK    131072
#define HW       4096
#define OFF_SCAL 8388608
#define OFF_IDX  8388613
#define THETA    1e-5f

// Scratch (static device globals: allocation-free).
// g_bprime: per code 192 bf16 = [eh(64) | em(64) | eh(64)], packed u32 pairs (96 words/row).
__device__ __align__(16) uint32_t g_bprime[512 * 96];
__device__ float        g_bnorm[512];
__device__ int          g_idx[N_TOK];
__device__ unsigned int g_counts[512];
__device__ double       g_dsum;
__device__ int          g_nflag;
__device__ int          g_flag[N_TOK];

// ---------------- helpers ----------------
__device__ __forceinline__ uint32_t smem_u32(const void* p) {
    uint32_t a;
    asm("{ .reg .u64 t; cvta.to.shared.u64 t, %1; cvt.u32.u64 %0, t; }"
        : "=r"(a) : "l"(p));
    return a;
}
__device__ __forceinline__ uint32_t packbf(float lo, float hi) {
    uint32_t r;
    asm("cvt.rn.bf16x2.f32 %0, %1, %2;" : "=r"(r) : "f"(hi), "f"(lo));
    return r;
}
__device__ __forceinline__ void ldsm4(uint32_t b[4], uint32_t addr) {
    asm volatile("ldmatrix.sync.aligned.m8n8.x4.shared.b16 {%0,%1,%2,%3}, [%4];"
                 : "=r"(b[0]), "=r"(b[1]), "=r"(b[2]), "=r"(b[3]) : "r"(addr));
}
__device__ __forceinline__ void mma16816(float c[4], const uint32_t a[4],
                                         uint32_t b0, uint32_t b1) {
    asm volatile("mma.sync.aligned.m16n8k16.row.col.f32.bf16.bf16.f32 "
                 "{%0,%1,%2,%3}, {%4,%5,%6,%7}, {%8,%9}, {%0,%1,%2,%3};"
                 : "+f"(c[0]), "+f"(c[1]), "+f"(c[2]), "+f"(c[3])
                 : "r"(a[0]), "r"(a[1]), "r"(a[2]), "r"(a[3]), "r"(b0), "r"(b1));
}

// ---- prep: code norms + split codebook [eh|em|eh] + zero accumulators ----
__global__ void vq_prep(const float* __restrict__ emb) {
    int k = blockIdx.x * 256 + threadIdx.x;   // 0..511
    const float* e = emb + k * 64;
    float s = 0.f;
    for (int d = 0; d < 64; ++d) s = fmaf(e[d], e[d], s);
    g_bnorm[k]  = s;
    g_counts[k] = 0u;
    if (k == 0) { g_dsum = 0.0; g_nflag = 0; }

    uint32_t* row = g_bprime + k * 96;
    for (int d = 0; d < 64; d += 2) {
        float v0 = e[d], v1 = e[d + 1];
        float h0 = __bfloat162float(__float2bfloat16(v0));
        float h1 = __bfloat162float(__float2bfloat16(v1));
        uint32_t eh = packbf(h0, h1);           // exact re-pack of rounded values
        uint32_t em = packbf(v0 - h0, v1 - h1);
        row[d / 2]      = eh;
        row[32 + d / 2] = em;
        row[64 + d / 2] = eh;
    }
}

// ---------------- main HMMA kernel ----------------
// smem (bytes): B' swizzled 512*384 = 196608 | bn 2048 | hist 2048
#define SM_B     0
#define SM_BN    196608
#define SM_HIST  (196608 + 2048)
#define SM_TOTAL (196608 + 2048 + 2048)

__global__ __launch_bounds__(256, 1)
void vq_main(const float* __restrict__ z_e, float* __restrict__ out) {
    extern __shared__ __align__(16) unsigned char smem[];
    const uint32_t sb  = smem_u32(smem);
    const int tid  = threadIdx.x;
    const int wid  = tid >> 5, lane = tid & 31;
    const int q    = lane >> 2;          // groupID
    const int c2   = (lane & 3) * 2;     // in-tile col base
    const int strip = wid * 32;

    // --- copy B' into smem with per-8-row XOR swizzle on 16B units ---
    for (int rr = 0; rr < 2; ++rr) {
        int row = rr * 256 + tid;
        const uint4* src = (const uint4*)(g_bprime + row * 96);
        int sw = row & 7;
#pragma unroll
        for (int u = 0; u < 24; ++u) {
            *(uint4*)(smem + SM_B + row * 384 + (((u & ~7) | ((u & 7) ^ sw)) << 4)) =
                src[u];
        }
    }
    for (int i = tid; i < 512; i += 256) {
        ((float*)(smem + SM_BN))[i]      = g_bnorm[i];
        ((uint32_t*)(smem + SM_HIST))[i] = 0u;
    }

    // --- A fragments straight from gmem (bf16 2-split) + token norms ---
    const int nbase = blockIdx.x * 256;
    const int b     = nbase >> 12;
    const int hwb   = nbase & (HW - 1);
    const float* zb = z_e + ((size_t)b << 18) + hwb;

    uint32_t ah[2][4][4], am[2][4][4];
    float    anr[4];
#pragma unroll
    for (int mt = 0; mt < 2; ++mt) {
#pragma unroll
        for (int i = 0; i < 2; ++i) {
            int row = strip + mt * 16 + i * 8 + q;
            const float* zp = zb + row;
            float acc = 0.f;
#pragma unroll
            for (int s = 0; s < 4; ++s) {
                int d0 = 16 * s + c2;
                float v0 = zp[(size_t)(d0    ) << 12];
                float v1 = zp[(size_t)(d0 + 1) << 12];
                float v2 = zp[(size_t)(d0 + 8) << 12];
                float v3 = zp[(size_t)(d0 + 9) << 12];
                acc = fmaf(v0, v0, acc); acc = fmaf(v1, v1, acc);
                acc = fmaf(v2, v2, acc); acc = fmaf(v3, v3, acc);
                float h0 = __bfloat162float(__float2bfloat16(v0));
                float h1 = __bfloat162float(__float2bfloat16(v1));
                float h2 = __bfloat162float(__float2bfloat16(v2));
                float h3 = __bfloat162float(__float2bfloat16(v3));
                ah[mt][s][i]     = packbf(h0, h1);
                ah[mt][s][i + 2] = packbf(h2, h3);
                am[mt][s][i]     = packbf(v0 - h0, v1 - h1);
                am[mt][s][i + 2] = packbf(v2 - h2, v3 - h3);
            }
            // full ||z||^2 for this row: sum the 4 quad lanes' partials
            acc += __shfl_xor_sync(0xffffffffu, acc, 1);
            acc += __shfl_xor_sync(0xffffffffu, acc, 2);
            anr[mt * 2 + i] = acc;
        }
    }
    __syncthreads();

    // --- per-lane ldmatrix addressing constants ---
    const int sub  = (lane >> 3) & 1;                       // k-half
    const int rc   = ((lane & 16) >> 1) + (lane & 7);       // row const within pair
    const int sw7  = lane & 7;
    uint32_t boff[12];
#pragma unroll
    for (int ks = 0; ks < 12; ++ks) {
        int u = 2 * ks + sub;
        boff[ks] = (uint32_t)(((u & ~7) | ((u & 7) ^ sw7)) << 4);
    }

    const float* bn = (const float*)(smem + SM_BN);
    float d1[4] = {FLT_MAX, FLT_MAX, FLT_MAX, FLT_MAX};
    float d2[4] = {FLT_MAX, FLT_MAX, FLT_MAX, FLT_MAX};
    int   i1[4] = {0, 0, 0, 0};

#pragma unroll 1
    for (int j = 0; j < 32; ++j) {      // 32 n-tile pairs = 64 n-tiles = 512 codes
        uint32_t bj = sb + SM_B + (uint32_t)(j * 16 + rc) * 384u;
        float c[2][2][4];
#pragma unroll
        for (int mt = 0; mt < 2; ++mt)
#pragma unroll
            for (int nt = 0; nt < 2; ++nt)
#pragma unroll
                for (int r = 0; r < 4; ++r) c[mt][nt][r] = 0.f;

#pragma unroll
        for (int ks = 0; ks < 12; ++ks) {
            uint32_t bf[4];
            ldsm4(bf, bj + boff[ks]);
            const uint32_t (*a)[4] = (ks < 8) ? ah[0] + 0 : am[0] + 0; // dummy init
            // select fragment set: ks 0-3 -> ah[mt][ks], 4-7 -> ah[mt][ks-4], 8-11 -> am[mt][ks-8]
#pragma unroll
            for (int mt = 0; mt < 2; ++mt) {
                const uint32_t* af =
                    (ks < 4) ? ah[mt][ks] : (ks < 8) ? ah[mt][ks - 4] : am[mt][ks - 8];
                mma16816(c[mt][0], af, bf[0], bf[1]);
                mma16816(c[mt][1], af, bf[2], bf[3]);
            }
            (void)a;
        }

        // epilogue for this pair: 16 codes x 4 rows held per quad
        int cb = j * 16 + c2;
        float bn0 = bn[cb],     bn1 = bn[cb + 1];
        float bn8 = bn[cb + 8], bn9 = bn[cb + 9];
#pragma unroll
        for (int mt = 0; mt < 2; ++mt)
#pragma unroll
            for (int half = 0; half < 2; ++half) {    // c0/c1 (row q) vs c2/c3 (row q+8)
                int r = mt * 2 + half;
                float A = anr[r];
                float v0 = fmaf(c[mt][0][half * 2],     -2.f, A + bn0);
                float v1 = fmaf(c[mt][0][half * 2 + 1], -2.f, A + bn1);
                float v2 = fmaf(c[mt][1][half * 2],     -2.f, A + bn8);
                float v3 = fmaf(c[mt][1][half * 2 + 1], -2.f, A + bn9);
                if (v0 < d1[r]) { d2[r] = d1[r]; d1[r] = v0; i1[r] = cb;     } else if (v0 < d2[r]) d2[r] = v0;
                if (v1 < d1[r]) { d2[r] = d1[r]; d1[r] = v1; i1[r] = cb + 1; } else if (v1 < d2[r]) d2[r] = v1;
                if (v2 < d1[r]) { d2[r] = d1[r]; d1[r] = v2; i1[r] = cb + 8; } else if (v2 < d2[r]) d2[r] = v2;
                if (v3 < d1[r]) { d2[r] = d1[r]; d1[r] = v3; i1[r] = cb + 9; } else if (v3 < d2[r]) d2[r] = v3;
            }
    }

    // --- merge top-2 across the 4 quad lanes (cols of each row) ---
    float dloc = 0.f;
#pragma unroll
    for (int r = 0; r < 4; ++r) {
#pragma unroll
        for (int o = 1; o <= 2; o <<= 1) {
            float od1 = __shfl_xor_sync(0xffffffffu, d1[r], o);
            int   oi1 = __shfl_xor_sync(0xffffffffu, i1[r], o);
            float od2 = __shfl_xor_sync(0xffffffffu, d2[r], o);
            if (od1 < d1[r] || (od1 == d1[r] && oi1 < i1[r])) {
                d2[r] = fminf(d1[r], od2);
                d1[r] = od1; i1[r] = oi1;
            } else {
                d2[r] = fminf(d2[r], od1);
            }
        }
        if ((lane & 3) == 0) {
            int rows[4] = {strip + q, strip + q + 8, strip + q + 16, strip + q + 24};
            int n = nbase + rows[r];
            if (d2[r] - d1[r] < THETA) {
                int pos = atomicAdd(&g_nflag, 1);
                g_flag[pos] = n;
            } else {
                g_idx[n]         = i1[r];
                out[OFF_IDX + n] = (float)i1[r];
                atomicAdd(((uint32_t*)(smem + SM_HIST)) + i1[r], 1u);
                dloc += d1[r];
            }
        }
    }
#pragma unroll
    for (int o = 16; o; o >>= 1) dloc += __shfl_xor_sync(0xffffffffu, dloc, o);
    if (lane == 0) atomicAdd(&g_dsum, (double)dloc);

    __syncthreads();
    for (int i = tid; i < 512; i += 256) {
        uint32_t h = ((uint32_t*)(smem + SM_HIST))[i];
        if (h) atomicAdd(&g_counts[i], h);
    }
}

// ---- exact fp32 rescan of flagged (near-tie) tokens ----
__global__ void vq_fix(const float* __restrict__ z_e, const float* __restrict__ emb,
                       float* __restrict__ out) {
    int gw   = (blockIdx.x * 256 + threadIdx.x) >> 5;
    int lane = threadIdx.x & 31;
    int nf   = g_nflag;
    for (int i = gw; i < nf; i += 1024) {
        int n = g_flag[i];
        const float* zp = z_e + ((size_t)(n >> 12) << 18) + (n & (HW - 1));
        float z[64];
        float A = 0.f;
#pragma unroll
        for (int d = 0; d < 64; ++d) {
            z[d] = zp[(size_t)d << 12];
            A = fmaf(z[d], z[d], A);
        }
        float dmin = FLT_MAX;
        int   imin = 0;
        for (int c = lane; c < 512; c += 32) {
            const float* e = emb + c * 64;
            float dot = 0.f;
#pragma unroll
            for (int d = 0; d < 64; ++d) dot = fmaf(z[d], e[d], dot);
            float dist = fmaf(dot, -2.f, A + g_bnorm[c]);
            if (dist < dmin) { dmin = dist; imin = c; }
        }
#pragma unroll
        for (int o = 16; o; o >>= 1) {
            float od = __shfl_xor_sync(0xffffffffu, dmin, o);
            int   oi = __shfl_xor_sync(0xffffffffu, imin, o);
            if (od < dmin || (od == dmin && oi < imin)) { dmin = od; imin = oi; }
        }
        if (lane == 0) {
            g_idx[n]         = imin;
            out[OFF_IDX + n] = (float)imin;
            atomicAdd(&g_counts[imin], 1u);
            atomicAdd(&g_dsum, (double)dmin);
        }
    }
}

// ---- z_q scatter: out[b,d,h,w] = emb[idx[b,h,w], d] ----
__global__ void vq_zq(const float* __restrict__ emb, float* __restrict__ out) {
    int t  = blockIdx.x * 256 + threadIdx.x;
    int hw = t & (HW - 1);
    int d4 = (t >> 12) & 15;
    int b  = t >> 16;
    int idx = g_idx[(b << 12) + hw];
    const float4 e = *(const float4*)(emb + idx * 64 + d4 * 4);
    int base = (b << 18) + (d4 << 14) + hw;
    out[base        ] = e.x;
    out[base +  4096] = e.y;
    out[base +  8192] = e.z;
    out[base + 12288] = e.w;
}

// ---- scalars ----
__global__ void vq_finalize(float* __restrict__ out) {
    __shared__ float s_e[16];
    __shared__ int   s_u[16];
    int k = threadIdx.x;
    unsigned int c = g_counts[k];
    float p = (float)c * (1.0f / 131072.0f);
    float e = (c > 0) ? -p * logf(p) : 0.0f;
    int   u = (c > 0) ? 1 : 0;
#pragma unroll
    for (int o = 16; o; o >>= 1) {
        e += __shfl_xor_sync(0xffffffffu, e, o);
        u += __shfl_xor_sync(0xffffffffu, u, o);
    }
    if ((k & 31) == 0) { s_e[k >> 5] = e; s_u[k >> 5] = u; }
    __syncthreads();
    if (k == 0) {
        float ent = 0.0f; int used = 0;
        for (int i = 0; i < 16; ++i) { ent += s_e[i]; used += s_u[i]; }
        float avg = (float)(g_dsum * (1.0 / 131072.0));
        out[OFF_SCAL + 0] = 1.25f * avg;
        out[OFF_SCAL + 1] = expf(ent);
        out[OFF_SCAL + 2] = (float)used;
        out[OFF_SCAL + 3] = (float)used / 512.0f;
        out[OFF_SCAL + 4] = avg;
    }
}

extern "C" void kernel_launch(void* const* d_in, const int* in_sizes, int n_in,
                              void* d_out, int out_size) {
    const float* z_e = (const float*)d_in[0];
    const float* emb = (const float*)d_in[1];
    float*       out = (float*)d_out;

    cudaFuncSetAttribute(vq_main, cudaFuncAttributeMaxDynamicSharedMemorySize,
                         SM_TOTAL);

    vq_prep<<<2, 256>>>(emb);
    vq_main<<<N_TOK / 256, 256, SM_TOTAL>>>(z_e, out);
    vq_fix<<<128, 256>>>(z_e, emb, out);
    vq_zq<<<(N_TOK * 16) / 256, 256>>>(emb, out);
    vq_finalize<<<1, 512>>>(out);
}